// round 11
// baseline (speedup 1.0000x reference)
#include <cuda_runtime.h>
#include <cstdint>

// CausalQueue: out[b, 0:C]  = (size == D) ? buffer[head, b, :] : 0
//              out[b, C:2C] = x[b, :]
// x: [B,C] f32, buffer: [D,B,C] f32, size/head int32 device scalars.
// D=128, B=2048, C=512. 16 MB total traffic; latency/launch-envelope bound.
//
// R10: single-wave, zero-tail config. grid = 128 blocks (<= 148 SMs, one
// block per SM, no second wave), block = 512 threads (16 warps/SM).
// Block covers 16 output rows; thread t owns column (t & 255) of rows
// row0 + (t >> 8) + 2k, k = 0..7 -> 8 independent front-batched LDG.128
// per thread (MLP_p1 = 8). Half-selection by lane: warp-uniform, and
// x-half warps never touch the device scalars.

#define D_CAP  128
#define B_DIM  2048
#define C4     128              // float4 per half-row (C=512)
#define ROW4   256              // float4 per output row
#define RPB    16               // rows per block
#define GRID   (B_DIM / RPB)    // 128 blocks
#define NLD    8                // independent loads per thread

__global__ void __launch_bounds__(512)
causal_queue_kernel(const float4* __restrict__ x,
                    const float4* __restrict__ buffer,
                    const int* __restrict__ size_p,
                    const int* __restrict__ head_p,
                    float4* __restrict__ out)
{
    const int t    = threadIdx.x;          // 0..511
    const int col  = t & 255;              // column in the 256-float4 row
    const int rsub = t >> 8;               // 0 or 1: row parity within block
    const int row0 = blockIdx.x * RPB + rsub;   // rows row0, row0+2, ... row0+14

    float4 v[NLD];

    if (col < C4) {
        // ---- past half: column col of buffer[head] (or zeros) ----
        const int  head = __ldg(head_p);
        const bool full = (__ldg(size_p) == D_CAP);
        if (full) {
            const float4* src = buffer + (size_t)head * (B_DIM * C4)
                                       + (size_t)row0 * C4 + col;
#pragma unroll
            for (int k = 0; k < NLD; k++) v[k] = src[(size_t)(2 * k) * C4];
        } else {
#pragma unroll
            for (int k = 0; k < NLD; k++) v[k] = make_float4(0.f, 0.f, 0.f, 0.f);
        }
    } else {
        // ---- x half: column col-128 of x ----
        const float4* src = x + (size_t)row0 * C4 + (col - C4);
#pragma unroll
        for (int k = 0; k < NLD; k++) v[k] = src[(size_t)(2 * k) * C4];
    }

    float4* dst = out + (size_t)row0 * ROW4 + col;
#pragma unroll
    for (int k = 0; k < NLD; k++) dst[(size_t)(2 * k) * ROW4] = v[k];
}

extern "C" void kernel_launch(void* const* d_in, const int* in_sizes, int n_in,
                              void* d_out, int out_size)
{
    const float4* x      = (const float4*)d_in[0];   // [B, C] f32
    const float4* buffer = (const float4*)d_in[1];   // [D, B, C] f32
    const int*    size_p = (const int*)d_in[2];      // scalar
    const int*    head_p = (const int*)d_in[3];      // scalar
    float4*       out    = (float4*)d_out;           // [B, 2C] f32

    causal_queue_kernel<<<GRID, 512>>>(x, buffer, size_p, head_p, out);
}

// round 13
// speedup vs baseline: 1.2035x; 1.2035x over previous
#include <cuda_runtime.h>
#include <cstdint>

// CausalQueue: out[b, 0:C]  = (size == D) ? buffer[head, b, :] : 0
//              out[b, C:2C] = x[b, :]
// x: [B,C] f32, buffer: [D,B,C] f32, size/head int32 device scalars.
// D=128, B=2048, C=512. 16 MB traffic; launch-envelope + latency bound.
//
// R11: shortest critical path. Past-half data loads are UNconditional
// (address = buffer[head & 127], always in-bounds); the (size == D)
// predicate selects data-vs-zero AFTER the loads return, so the size
// load runs in parallel with the head->data chain instead of guarding
// it. Shape: grid 512 x 256 (full-chip TLP, ~3.5 blocks/SM), 4 rows
// per block, 4 independent front-batched LDG.128 per thread.

#define D_CAP  128
#define B_DIM  2048
#define C4     128              // float4 per half-row (C=512)
#define ROW4   256              // float4 per output row
#define RPB    4                // rows per block
#define GRID   (B_DIM / RPB)    // 512

__global__ void __launch_bounds__(256)
causal_queue_kernel(const float4* __restrict__ x,
                    const float4* __restrict__ buffer,
                    const int* __restrict__ size_p,
                    const int* __restrict__ head_p,
                    float4* __restrict__ out)
{
    const int t    = threadIdx.x;        // 0..255 = column in output row
    const int row0 = blockIdx.x * RPB;

    float4 v[RPB];

    if (t < C4) {
        // ---- past half, column t: always load, select afterwards ----
        const int head = __ldg(head_p) & (D_CAP - 1);   // in-bounds for any input
        const float4* src = buffer + (size_t)head * (B_DIM * C4)
                                   + (size_t)row0 * C4 + t;
#pragma unroll
        for (int k = 0; k < RPB; k++) v[k] = src[k * C4];   // front-batched, MLP=4

        // size load overlaps the data loads; select applied post-return.
        const float m = (__ldg(size_p) == D_CAP) ? 1.0f : 0.0f;
#pragma unroll
        for (int k = 0; k < RPB; k++) {
            v[k].x *= m; v[k].y *= m; v[k].z *= m; v[k].w *= m;
        }
    } else {
        // ---- x half, column t-128: no scalar dependence at all ----
        const float4* src = x + (size_t)row0 * C4 + (t - C4);
#pragma unroll
        for (int k = 0; k < RPB; k++) v[k] = src[k * C4];
    }

    float4* dst = out + (size_t)row0 * ROW4 + t;
#pragma unroll
    for (int k = 0; k < RPB; k++) dst[k * ROW4] = v[k];
}

extern "C" void kernel_launch(void* const* d_in, const int* in_sizes, int n_in,
                              void* d_out, int out_size)
{
    const float4* x      = (const float4*)d_in[0];   // [B, C] f32
    const float4* buffer = (const float4*)d_in[1];   // [D, B, C] f32
    const int*    size_p = (const int*)d_in[2];      // scalar
    const int*    head_p = (const int*)d_in[3];      // scalar
    float4*       out    = (float4*)d_out;           // [B, 2C] f32

    causal_queue_kernel<<<GRID, 256>>>(x, buffer, size_p, head_p, out);
}

// round 14
// speedup vs baseline: 1.3077x; 1.0865x over previous
#include <cuda_runtime.h>
#include <cstdint>

// CausalQueue: out[b, 0:C]  = (size == D) ? buffer[head, b, :] : 0
//              out[b, C:2C] = x[b, :]
// x: [B,C] f32, buffer: [D,B,C] f32, size/head int32 device scalars.
// D=128, B=2048, C=512. 16 MB traffic; replay-envelope + latency bound.
//
// R13 (final shape): R11 body with the data-vs-zero selection moved from
// an FMUL mask to a uniform branch at store time. The size load (4 B,
// cache-hit) returns far before the 4 MB of data loads, so the branch
// predicate is free by store time; the not-full path's stores don't wait
// on the data loads at all. Shape: grid 512 x 256 (full-chip TLP,
// ~3.5 blocks/SM), 4 rows/block, 4 independent front-batched LDG.128
// per thread; x-half warps never touch the scalars.

#define D_CAP  128
#define B_DIM  2048
#define C4     128              // float4 per half-row (C=512)
#define ROW4   256              // float4 per output row
#define RPB    4                // rows per block
#define GRID   (B_DIM / RPB)    // 512

__global__ void __launch_bounds__(256)
causal_queue_kernel(const float4* __restrict__ x,
                    const float4* __restrict__ buffer,
                    const int* __restrict__ size_p,
                    const int* __restrict__ head_p,
                    float4* __restrict__ out)
{
    const int t    = threadIdx.x;        // 0..255 = column in output row
    const int row0 = blockIdx.x * RPB;

    if (t < C4) {
        // ---- past half, column t ----
        // Scalar loads issued first; size result is consumed only at
        // store-select time, head feeds the (unconditional) address.
        const int  size = __ldg(size_p);
        const int  head = __ldg(head_p) & (D_CAP - 1);  // in-bounds for any input

        const float4* src = buffer + (size_t)head * (B_DIM * C4)
                                   + (size_t)row0 * C4 + t;
        float4 v[RPB];
#pragma unroll
        for (int k = 0; k < RPB; k++) v[k] = src[k * C4];   // front-batched, MLP=4

        float4* dst = out + (size_t)row0 * ROW4 + t;
        if (size == D_CAP) {            // uniform across grid: no divergence
#pragma unroll
            for (int k = 0; k < RPB; k++) dst[k * ROW4] = v[k];
        } else {
            const float4 z = make_float4(0.f, 0.f, 0.f, 0.f);
#pragma unroll
            for (int k = 0; k < RPB; k++) dst[k * ROW4] = z;
        }
    } else {
        // ---- x half, column t-128: no scalar dependence at all ----
        const float4* src = x + (size_t)row0 * C4 + (t - C4);
        float4 v[RPB];
#pragma unroll
        for (int k = 0; k < RPB; k++) v[k] = src[k * C4];

        float4* dst = out + (size_t)row0 * ROW4 + t;
#pragma unroll
        for (int k = 0; k < RPB; k++) dst[k * ROW4] = v[k];
    }
}

extern "C" void kernel_launch(void* const* d_in, const int* in_sizes, int n_in,
                              void* d_out, int out_size)
{
    const float4* x      = (const float4*)d_in[0];   // [B, C] f32
    const float4* buffer = (const float4*)d_in[1];   // [D, B, C] f32
    const int*    size_p = (const int*)d_in[2];      // scalar
    const int*    head_p = (const int*)d_in[3];      // scalar
    float4*       out    = (float4*)d_out;           // [B, 2C] f32

    causal_queue_kernel<<<GRID, 256>>>(x, buffer, size_p, head_p, out);
}